// round 2
// baseline (speedup 1.0000x reference)
#include <cuda_runtime.h>

// Problem constants (fixed by reference): B=16, C=4, H=W=640
#define NB   16
#define NC   4
#define PIX  409600                // 640*640
#define NTAG 8                     // tags 1..8 (tag 0 provably never contributes)
#define CPB  50                    // CTAs per batch
#define TPB  256
#define CHUNK (PIX / CPB)          // 8192 pixels per CTA
#define ITERS (CHUNK / (TPB * 4))  // 8 iterations of 4-pixel vectors

// ---------------- scratch (device globals; no allocation) ----------------
__device__ float    g_ksum[NB][NTAG][NC];
__device__ float    g_kcnt[NB][NTAG];
__device__ float    g_tsum[NB][NTAG];
__device__ float    g_tcnt[NB][NTAG];
__device__ unsigned g_presK[NB];
__device__ unsigned g_presT[NB];

// ---------------- helpers ----------------
__device__ __forceinline__ float f4get(const float4& v, int j) {
    return j == 0 ? v.x : (j == 1 ? v.y : (j == 2 ? v.z : v.w));
}
__device__ __forceinline__ float wsum(float v) {
#pragma unroll
    for (int o = 16; o; o >>= 1) v += __shfl_down_sync(0xffffffffu, v, o);
    return v;
}

// ---------------- kernel 0: zero scratch ----------------
__global__ void zero_scratch() {
    int i = threadIdx.x;
    float* ks = &g_ksum[0][0][0];
#pragma unroll
    for (int j = i; j < NB * NTAG * NC; j += TPB) ks[j] = 0.f;
    float* kc = &g_kcnt[0][0];
    float* ts = &g_tsum[0][0];
    float* tc = &g_tcnt[0][0];
    if (i < NB * NTAG) { kc[i] = 0.f; ts[i] = 0.f; tc[i] = 0.f; }
    if (i < NB) { g_presK[i] = 0u; g_presT[i] = 0u; }
}

// ---------------- kernel 1: kernel-mean sums + masked presence ----------------
__global__ void __launch_bounds__(TPB) pass1(
    const int* __restrict__ text, const int* __restrict__ kern,
    const int* __restrict__ mask, const float* __restrict__ sv)
{
    const int b   = blockIdx.y;
    const int tid = threadIdx.x;

    float s[NTAG][NC];
    float cnt[NTAG];
#pragma unroll
    for (int t = 0; t < NTAG; t++) {
        cnt[t] = 0.f;
#pragma unroll
        for (int c = 0; c < NC; c++) s[t][c] = 0.f;
    }
    unsigned pk = 0u, pt = 0u;

    const int base = b * PIX;
    const int svb  = b * NC * PIX;
    const int off0 = blockIdx.x * CHUNK + tid * 4;

#pragma unroll
    for (int it = 0; it < ITERS; ++it) {
        const int i = off0 + it * (TPB * 4);
        const int4 kk = *(const int4*)(kern + base + i);
        const int4 tt = *(const int4*)(text + base + i);
        const int4 mm = *(const int4*)(mask + base + i);
        float4 v[NC];
#pragma unroll
        for (int c = 0; c < NC; c++)
            v[c] = *(const float4*)(sv + svb + c * PIX + i);

        const int ka[4] = {kk.x, kk.y, kk.z, kk.w};
        const int ta[4] = {tt.x, tt.y, tt.z, tt.w};
        const int ma[4] = {mm.x, mm.y, mm.z, mm.w};

#pragma unroll
        for (int j = 0; j < 4; j++) {
            const int tk = ka[j], tx = ta[j];
            const unsigned mbit = (ma[j] != 0) ? ~0u : 0u;  // branchless presence
            pk |= (1u << tk) & mbit;
            pt |= (1u << tx) & mbit;
            const float x0 = f4get(v[0], j), x1 = f4get(v[1], j);
            const float x2 = f4get(v[2], j), x3 = f4get(v[3], j);
#pragma unroll
            for (int t = 1; t <= NTAG; t++) {
                if (tk == t) {
                    cnt[t - 1] += 1.f;
                    s[t - 1][0] += x0; s[t - 1][1] += x1;
                    s[t - 1][2] += x2; s[t - 1][3] += x3;
                }
            }
        }
    }
    pk &= ~1u;  // bit 0 (background / masked-out) never counts
    pt &= ~1u;

    // warp reduce 40 floats + 2 OR-masks
    float red[NTAG * NC + NTAG];
#pragma unroll
    for (int t = 0; t < NTAG; t++) {
#pragma unroll
        for (int c = 0; c < NC; c++) red[t * NC + c] = s[t][c];
        red[NTAG * NC + t] = cnt[t];
    }
#pragma unroll
    for (int k = 0; k < NTAG * NC + NTAG; k++) red[k] = wsum(red[k]);
    pk = __reduce_or_sync(0xffffffffu, pk);
    pt = __reduce_or_sync(0xffffffffu, pt);

    __shared__ float    shacc[NTAG * NC + NTAG];
    __shared__ unsigned shp[2];
    if (tid < NTAG * NC + NTAG) shacc[tid] = 0.f;
    if (tid < 2) shp[tid] = 0u;
    __syncthreads();
    if ((tid & 31) == 0) {
#pragma unroll
        for (int k = 0; k < NTAG * NC + NTAG; k++) atomicAdd(&shacc[k], red[k]);
        atomicOr(&shp[0], pk);
        atomicOr(&shp[1], pt);
    }
    __syncthreads();
    if (tid < NTAG * NC) {
        atomicAdd(&g_ksum[b][tid >> 2][tid & 3], shacc[tid]);
    } else if (tid < NTAG * NC + NTAG) {
        atomicAdd(&g_kcnt[b][tid - NTAG * NC], shacc[tid]);
    } else if (tid == NTAG * NC + NTAG) {
        atomicOr(&g_presK[b], shp[0]);
    } else if (tid == NTAG * NC + NTAG + 1) {
        atomicOr(&g_presT[b], shp[1]);
    }
}

// ---------------- kernel 2: per-pixel hinge loss, segment sums over text ----------------
__global__ void __launch_bounds__(TPB) pass2(
    const int* __restrict__ text, const float* __restrict__ sv)
{
    // reverse order: start with the data pass1 touched last (still in L2)
    const int b   = (NB - 1) - blockIdx.y;
    const int chk = (CPB - 1) - blockIdx.x;
    const int tid = threadIdx.x;

    __shared__ float km[NTAG][NC];
    if (tid < NTAG * NC) {
        const int t = tid >> 2, c = tid & 3;
        km[t][c] = g_ksum[b][t][c] / fmaxf(g_kcnt[b][t], 1.f);
    }
    __syncthreads();

    float ts[NTAG], tc[NTAG];
#pragma unroll
    for (int t = 0; t < NTAG; t++) { ts[t] = 0.f; tc[t] = 0.f; }

    const int base = b * PIX;
    const int svb  = b * NC * PIX;
    const int off0 = chk * CHUNK + tid * 4;

#pragma unroll
    for (int it = 0; it < ITERS; ++it) {
        const int i = off0 + it * (TPB * 4);
        const int4 tt = *(const int4*)(text + base + i);
        float4 v[NC];
#pragma unroll
        for (int c = 0; c < NC; c++)
            v[c] = *(const float4*)(sv + svb + c * PIX + i);
        const int ta[4] = {tt.x, tt.y, tt.z, tt.w};

#pragma unroll
        for (int j = 0; j < 4; j++) {
            const int tx = ta[j];
            if (tx != 0) {
                const float d0 = f4get(v[0], j) - km[tx - 1][0];
                const float d1 = f4get(v[1], j) - km[tx - 1][1];
                const float d2 = f4get(v[2], j) - km[tx - 1][2];
                const float d3 = f4get(v[3], j) - km[tx - 1][3];
                const float ss = fmaf(d0, d0, fmaf(d1, d1, fmaf(d2, d2, d3 * d3)));
                const float dist = sqrtf(fmaxf(ss, 1e-12f));
                const float h = fmaxf(dist - 0.5f, 0.f);
                const float L = __logf(fmaf(h, h, 1.f));
#pragma unroll
                for (int t = 1; t <= NTAG; t++) {
                    if (tx == t) { ts[t - 1] += L; tc[t - 1] += 1.f; }
                }
            }
        }
    }

    float red[2 * NTAG];
#pragma unroll
    for (int t = 0; t < NTAG; t++) { red[t] = ts[t]; red[NTAG + t] = tc[t]; }
#pragma unroll
    for (int k = 0; k < 2 * NTAG; k++) red[k] = wsum(red[k]);

    __shared__ float shacc[2 * NTAG];
    if (tid < 2 * NTAG) shacc[tid] = 0.f;
    __syncthreads();
    if ((tid & 31) == 0) {
#pragma unroll
        for (int k = 0; k < 2 * NTAG; k++) atomicAdd(&shacc[k], red[k]);
    }
    __syncthreads();
    if (tid < NTAG) {
        atomicAdd(&g_tsum[b][tid], shacc[tid]);
    } else if (tid < 2 * NTAG) {
        atomicAdd(&g_tcnt[b][tid - NTAG], shacc[tid]);
    }
}

// ---------------- kernel 3: final scalar reduction ----------------
__global__ void final_reduce(float* __restrict__ out) {
    const int b = threadIdx.x;  // 32 lanes, first 16 are batches
    float contrib = 0.f, valid = 0.f;
    if (b < NB) {
        const unsigned pk = g_presK[b] & 0x1FEu;
        const unsigned pt = g_presT[b] & 0x1FEu;
        const int nk = __popc(pk), nt = __popc(pt);
        const bool bval = (nk >= 1) && (nt >= 1) && (nk == nt);
        const unsigned tv = pk & pt;
        float sum = 0.f;
        int nv = 0;
#pragma unroll
        for (int t = 1; t <= NTAG; t++) {
            if ((tv >> t) & 1u) {
                sum += g_tsum[b][t - 1] / fmaxf(g_tcnt[b][t - 1], 1.f);
                nv++;
            }
        }
        const float per = (nv > 0) ? sum / (float)nv : 0.f;
        contrib = bval ? per : 0.f;
        valid   = bval ? 1.f : 0.f;
    }
    contrib = wsum(contrib);
    valid   = wsum(valid);
    if (b == 0) out[0] = (valid > 0.f) ? contrib / valid : 0.f;
}

// ---------------- launch ----------------
extern "C" void kernel_launch(void* const* d_in, const int* in_sizes, int n_in,
                              void* d_out, int out_size) {
    const int*   text = (const int*)d_in[0];   // gt_text_key
    const int*   kern = (const int*)d_in[1];   // gt_kernel_key
    const int*   mask = (const int*)d_in[2];   // training_mask
    const float* sv   = (const float*)d_in[3]; // similarity_vector
    float* out = (float*)d_out;

    zero_scratch<<<1, TPB>>>();
    pass1<<<dim3(CPB, NB), TPB>>>(text, kern, mask, sv);
    pass2<<<dim3(CPB, NB), TPB>>>(text, sv);
    final_reduce<<<1, 32>>>(out);
}

// round 3
// speedup vs baseline: 1.9517x; 1.9517x over previous
#include <cuda_runtime.h>

// Problem constants (fixed by reference): B=16, C=4, H=W=640
#define NB   16
#define NC   4
#define PIX  409600                // 640*640
#define NTAG 8                     // tags 1..8 (tag 0 provably never contributes)
#define CPB  100                   // CTAs per batch
#define TPB  256
#define CHUNK (PIX / CPB)          // 4096 pixels per CTA
#define ITERS (CHUNK / (TPB * 4))  // 4 iterations of 4-pixel vectors

// ---------------- scratch (device globals; zero-init at load; re-zeroed each call) ----------------
__device__ float    g_ksum[NB][NTAG][NC];
__device__ float    g_kcnt[NB][NTAG];
__device__ float    g_tsum[NB][NTAG];
__device__ float    g_tcnt[NB][NTAG];
__device__ unsigned g_presK[NB];
__device__ unsigned g_presT[NB];

// ---------------- helpers ----------------
__device__ __forceinline__ float f4get(const float4& v, int j) {
    return j == 0 ? v.x : (j == 1 ? v.y : (j == 2 ? v.z : v.w));
}
__device__ __forceinline__ float wsum(float v) {
#pragma unroll
    for (int o = 16; o; o >>= 1) v += __shfl_down_sync(0xffffffffu, v, o);
    return v;
}

// ---------------- kernel 1: kernel-mean sums + masked presence ----------------
__global__ void __launch_bounds__(TPB) pass1(
    const int* __restrict__ text, const int* __restrict__ kern,
    const int* __restrict__ mask, const float* __restrict__ sv)
{
    const int b   = blockIdx.y;
    const int tid = threadIdx.x;

    float s[NTAG][NC];
    float cnt[NTAG];
#pragma unroll
    for (int t = 0; t < NTAG; t++) {
        cnt[t] = 0.f;
#pragma unroll
        for (int c = 0; c < NC; c++) s[t][c] = 0.f;
    }
    unsigned pk = 0u, pt = 0u;

    const int base = b * PIX;
    const int svb  = b * NC * PIX;
    const int off0 = blockIdx.x * CHUNK + tid * 4;

#pragma unroll
    for (int it = 0; it < ITERS; ++it) {
        const int i = off0 + it * (TPB * 4);
        const int4 kk = *(const int4*)(kern + base + i);
        const int4 tt = *(const int4*)(text + base + i);
        const int4 mm = *(const int4*)(mask + base + i);
        float4 v[NC];
#pragma unroll
        for (int c = 0; c < NC; c++)
            v[c] = *(const float4*)(sv + svb + c * PIX + i);

        const int ka[4] = {kk.x, kk.y, kk.z, kk.w};
        const int ta[4] = {tt.x, tt.y, tt.z, tt.w};
        const int ma[4] = {mm.x, mm.y, mm.z, mm.w};

#pragma unroll
        for (int j = 0; j < 4; j++) {
            const int tk = ka[j], tx = ta[j];
            const unsigned mbit = (ma[j] != 0) ? ~0u : 0u;  // branchless presence
            pk |= (1u << tk) & mbit;
            pt |= (1u << tx) & mbit;
            const float x0 = f4get(v[0], j), x1 = f4get(v[1], j);
            const float x2 = f4get(v[2], j), x3 = f4get(v[3], j);
            // branchless one-hot accumulate: ISETP + FSEL + FFMA, no divergence
#pragma unroll
            for (int t = 0; t < NTAG; t++) {
                const float w = (tk == t + 1) ? 1.f : 0.f;
                cnt[t] += w;
                s[t][0] = fmaf(w, x0, s[t][0]);
                s[t][1] = fmaf(w, x1, s[t][1]);
                s[t][2] = fmaf(w, x2, s[t][2]);
                s[t][3] = fmaf(w, x3, s[t][3]);
            }
        }
    }
    pk &= ~1u;  // tag 0 never counts
    pt &= ~1u;

    // warp reduce 40 floats + 2 OR-masks
    float red[NTAG * NC + NTAG];
#pragma unroll
    for (int t = 0; t < NTAG; t++) {
#pragma unroll
        for (int c = 0; c < NC; c++) red[t * NC + c] = s[t][c];
        red[NTAG * NC + t] = cnt[t];
    }
#pragma unroll
    for (int k = 0; k < NTAG * NC + NTAG; k++) red[k] = wsum(red[k]);
    pk = __reduce_or_sync(0xffffffffu, pk);
    pt = __reduce_or_sync(0xffffffffu, pt);

    __shared__ float    shacc[NTAG * NC + NTAG];
    __shared__ unsigned shp[2];
    if (tid < NTAG * NC + NTAG) shacc[tid] = 0.f;
    if (tid < 2) shp[tid] = 0u;
    __syncthreads();
    if ((tid & 31) == 0) {
#pragma unroll
        for (int k = 0; k < NTAG * NC + NTAG; k++) atomicAdd(&shacc[k], red[k]);
        atomicOr(&shp[0], pk);
        atomicOr(&shp[1], pt);
    }
    __syncthreads();
    if (tid < NTAG * NC) {
        atomicAdd(&g_ksum[b][tid >> 2][tid & 3], shacc[tid]);
    } else if (tid < NTAG * NC + NTAG) {
        atomicAdd(&g_kcnt[b][tid - NTAG * NC], shacc[tid]);
    } else if (tid == NTAG * NC + NTAG) {
        atomicOr(&g_presK[b], shp[0]);
    } else if (tid == NTAG * NC + NTAG + 1) {
        atomicOr(&g_presT[b], shp[1]);
    }
}

// ---------------- kernel 2: per-pixel hinge loss, segment sums over text ----------------
__global__ void __launch_bounds__(TPB) pass2(
    const int* __restrict__ text, const float* __restrict__ sv)
{
    // reverse order: start with the data pass1 touched last (still in L2)
    const int b   = (NB - 1) - blockIdx.y;
    const int chk = (CPB - 1) - blockIdx.x;
    const int tid = threadIdx.x;

    __shared__ float4 km[NTAG];   // one LDS.128 per gather
    if (tid < NTAG) {
        const float inv = 1.f / fmaxf(g_kcnt[b][tid], 1.f);
        km[tid] = make_float4(g_ksum[b][tid][0] * inv, g_ksum[b][tid][1] * inv,
                              g_ksum[b][tid][2] * inv, g_ksum[b][tid][3] * inv);
    }
    __syncthreads();

    float ts[NTAG], tc[NTAG];
#pragma unroll
    for (int t = 0; t < NTAG; t++) { ts[t] = 0.f; tc[t] = 0.f; }

    const int base = b * PIX;
    const int svb  = b * NC * PIX;
    const int off0 = chk * CHUNK + tid * 4;

#pragma unroll
    for (int it = 0; it < ITERS; ++it) {
        const int i = off0 + it * (TPB * 4);
        const int4 tt = *(const int4*)(text + base + i);
        float4 v[NC];
#pragma unroll
        for (int c = 0; c < NC; c++)
            v[c] = *(const float4*)(sv + svb + c * PIX + i);
        const int ta[4] = {tt.x, tt.y, tt.z, tt.w};

#pragma unroll
        for (int j = 0; j < 4; j++) {
            const int tx = ta[j];
            const int ix = (tx != 0) ? tx - 1 : 0;          // safe gather index
            const float4 m = km[ix];
            const float d0 = f4get(v[0], j) - m.x;
            const float d1 = f4get(v[1], j) - m.y;
            const float d2 = f4get(v[2], j) - m.z;
            const float d3 = f4get(v[3], j) - m.w;
            const float ss = fmaf(d0, d0, fmaf(d1, d1, fmaf(d2, d2, d3 * d3)));
            const float dist = sqrtf(fmaxf(ss, 1e-12f));
            const float h = fmaxf(dist - 0.5f, 0.f);
            const float L = __logf(fmaf(h, h, 1.f));
            // branchless per-tag accumulate (tx==0 matches no tag -> zero weight)
#pragma unroll
            for (int t = 0; t < NTAG; t++) {
                const float w = (tx == t + 1) ? 1.f : 0.f;
                ts[t] = fmaf(w, L, ts[t]);
                tc[t] += w;
            }
        }
    }

    float red[2 * NTAG];
#pragma unroll
    for (int t = 0; t < NTAG; t++) { red[t] = ts[t]; red[NTAG + t] = tc[t]; }
#pragma unroll
    for (int k = 0; k < 2 * NTAG; k++) red[k] = wsum(red[k]);

    __shared__ float shacc[2 * NTAG];
    if (tid < 2 * NTAG) shacc[tid] = 0.f;
    __syncthreads();
    if ((tid & 31) == 0) {
#pragma unroll
        for (int k = 0; k < 2 * NTAG; k++) atomicAdd(&shacc[k], red[k]);
    }
    __syncthreads();
    if (tid < NTAG) {
        atomicAdd(&g_tsum[b][tid], shacc[tid]);
    } else if (tid < 2 * NTAG) {
        atomicAdd(&g_tcnt[b][tid - NTAG], shacc[tid]);
    }
}

// ---------------- kernel 3: final scalar reduction + scratch re-zero ----------------
__global__ void final_reduce(float* __restrict__ out) {
    const int b = threadIdx.x;  // 32 lanes, first 16 are batches
    float contrib = 0.f, valid = 0.f;
    if (b < NB) {
        const unsigned pk = g_presK[b] & 0x1FEu;
        const unsigned pt = g_presT[b] & 0x1FEu;
        const int nk = __popc(pk), nt = __popc(pt);
        const bool bval = (nk >= 1) && (nt >= 1) && (nk == nt);
        const unsigned tv = pk & pt;
        float sum = 0.f;
        int nv = 0;
#pragma unroll
        for (int t = 1; t <= NTAG; t++) {
            if ((tv >> t) & 1u) {
                sum += g_tsum[b][t - 1] / fmaxf(g_tcnt[b][t - 1], 1.f);
                nv++;
            }
        }
        const float per = (nv > 0) ? sum / (float)nv : 0.f;
        contrib = bval ? per : 0.f;
        valid   = bval ? 1.f : 0.f;
    }
    contrib = wsum(contrib);
    valid   = wsum(valid);
    if (b == 0) out[0] = (valid > 0.f) ? contrib / valid : 0.f;

    // re-zero scratch for the next call (device globals are zero at load,
    // so every kernel_launch invocation sees zeros)
    float* ks = &g_ksum[0][0][0];
#pragma unroll
    for (int j = b; j < NB * NTAG * NC; j += 32) ks[j] = 0.f;
#pragma unroll
    for (int j = b; j < NB * NTAG; j += 32) {
        (&g_kcnt[0][0])[j] = 0.f;
        (&g_tsum[0][0])[j] = 0.f;
        (&g_tcnt[0][0])[j] = 0.f;
    }
    if (b < NB) { g_presK[b] = 0u; g_presT[b] = 0u; }
}

// ---------------- launch ----------------
extern "C" void kernel_launch(void* const* d_in, const int* in_sizes, int n_in,
                              void* d_out, int out_size) {
    const int*   text = (const int*)d_in[0];   // gt_text_key
    const int*   kern = (const int*)d_in[1];   // gt_kernel_key
    const int*   mask = (const int*)d_in[2];   // training_mask
    const float* sv   = (const float*)d_in[3]; // similarity_vector
    float* out = (float*)d_out;

    pass1<<<dim3(CPB, NB), TPB>>>(text, kern, mask, sv);
    pass2<<<dim3(CPB, NB), TPB>>>(text, sv);
    final_reduce<<<1, 32>>>(out);
}

// round 4
// speedup vs baseline: 2.2115x; 1.1332x over previous
#include <cuda_runtime.h>

// Problem constants (fixed by reference): B=16, C=4, H=W=640
#define NB   16
#define NC   4
#define PIX  409600                // 640*640
#define NTAG 8                     // tags 1..8 (tag 0 provably never contributes)
#define CPB  80                    // CTAs per batch
#define TPB  256
#define CHUNK (PIX / CPB)          // 5120 pixels per CTA
#define ITERS (CHUNK / (TPB * 4))  // 5 iterations of 4-pixel vectors

// ---------------- scratch (device globals; zero at load; re-zeroed each call) ----------------
__device__ float    g_ksum[NB][NTAG][NC];
__device__ float    g_kcnt[NB][NTAG];
__device__ float    g_tsum[NB][NTAG];
__device__ float    g_tcnt[NB][NTAG];
__device__ unsigned g_presK[NB];
__device__ unsigned g_presT[NB];

// ---------------- helpers ----------------
typedef unsigned long long u64;

__device__ __forceinline__ u64 pack2(float lo, float hi) {
    u64 r; asm("mov.b64 %0, {%1, %2};" : "=l"(r) : "f"(lo), "f"(hi)); return r;
}
__device__ __forceinline__ void fma2(u64& d, u64 a, u64 b) {
    asm("fma.rn.f32x2 %0, %1, %2, %0;" : "+l"(d) : "l"(a), "l"(b));
}
__device__ __forceinline__ float2 unpack2(u64 v) {
    float2 f; asm("mov.b64 {%0, %1}, %2;" : "=f"(f.x), "=f"(f.y) : "l"(v)); return f;
}
__device__ __forceinline__ float f4get(const float4& v, int j) {
    return j == 0 ? v.x : (j == 1 ? v.y : (j == 2 ? v.z : v.w));
}
__device__ __forceinline__ float wsum(float v) {
#pragma unroll
    for (int o = 16; o; o >>= 1) v += __shfl_down_sync(0xffffffffu, v, o);
    return v;
}

// ---------------- kernel 1: kernel-mean sums + masked-kern presence ----------------
__global__ void __launch_bounds__(TPB, 3) pass1(
    const int* __restrict__ kern, const int* __restrict__ mask,
    const float* __restrict__ sv)
{
    const int b   = blockIdx.y;
    const int tid = threadIdx.x;

    u64 s01[NTAG], s23[NTAG];     // packed (c0,c1) and (c2,c3) sums per tag
    float cnt[NTAG];
#pragma unroll
    for (int t = 0; t < NTAG; t++) { s01[t] = 0ull; s23[t] = 0ull; cnt[t] = 0.f; }
    unsigned pk = 0u;

    const int base = b * PIX;
    const int svb  = b * NC * PIX;
    const int off0 = blockIdx.x * CHUNK + tid * 4;

#pragma unroll 1
    for (int it = 0; it < ITERS; ++it) {
        const int i = off0 + it * (TPB * 4);
        const int4 kk = *(const int4*)(kern + base + i);
        const int4 mm = *(const int4*)(mask + base + i);
        float4 v[NC];
#pragma unroll
        for (int c = 0; c < NC; c++)
            v[c] = *(const float4*)(sv + svb + c * PIX + i);

        const int ka[4] = {kk.x, kk.y, kk.z, kk.w};
        const int ma[4] = {mm.x, mm.y, mm.z, mm.w};

#pragma unroll
        for (int j = 0; j < 4; j++) {
            const int tk = ka[j];
            const unsigned mbit = (ma[j] != 0) ? ~0u : 0u;
            pk |= (1u << tk) & mbit;
            const u64 x01 = pack2(f4get(v[0], j), f4get(v[1], j));
            const u64 x23 = pack2(f4get(v[2], j), f4get(v[3], j));
#pragma unroll
            for (int t = 0; t < NTAG; t++) {
                const float w = (tk == t + 1) ? 1.f : 0.f;
                cnt[t] += w;
                const u64 wp = pack2(w, w);
                fma2(s01[t], wp, x01);
                fma2(s23[t], wp, x23);
            }
        }
    }
    pk &= ~1u;  // tag 0 never counts

    // warp reduce 40 floats + OR-mask
    float red[NTAG * NC + NTAG];
#pragma unroll
    for (int t = 0; t < NTAG; t++) {
        const float2 a = unpack2(s01[t]);
        const float2 c = unpack2(s23[t]);
        red[t * NC + 0] = a.x; red[t * NC + 1] = a.y;
        red[t * NC + 2] = c.x; red[t * NC + 3] = c.y;
        red[NTAG * NC + t] = cnt[t];
    }
#pragma unroll
    for (int k = 0; k < NTAG * NC + NTAG; k++) red[k] = wsum(red[k]);
    pk = __reduce_or_sync(0xffffffffu, pk);

    __shared__ float    shacc[NTAG * NC + NTAG];
    __shared__ unsigned shp;
    if (tid < NTAG * NC + NTAG) shacc[tid] = 0.f;
    if (tid == 0) shp = 0u;
    __syncthreads();
    if ((tid & 31) == 0) {
#pragma unroll
        for (int k = 0; k < NTAG * NC + NTAG; k++) atomicAdd(&shacc[k], red[k]);
        atomicOr(&shp, pk);
    }
    __syncthreads();
    if (tid < NTAG * NC) {
        atomicAdd(&g_ksum[b][tid >> 2][tid & 3], shacc[tid]);
    } else if (tid < NTAG * NC + NTAG) {
        atomicAdd(&g_kcnt[b][tid - NTAG * NC], shacc[tid]);
    } else if (tid == NTAG * NC + NTAG) {
        atomicOr(&g_presK[b], shp);
    }
}

// ---------------- kernel 2: per-pixel hinge loss + masked-text presence ----------------
__global__ void __launch_bounds__(TPB, 4) pass2(
    const int* __restrict__ text, const int* __restrict__ mask,
    const float* __restrict__ sv)
{
    // reverse order: start with the data pass1 touched last (still in L2)
    const int b   = (NB - 1) - blockIdx.y;
    const int chk = (CPB - 1) - blockIdx.x;
    const int tid = threadIdx.x;

    __shared__ float4 km[NTAG];   // one LDS.128 per gather
    if (tid < NTAG) {
        const float inv = 1.f / fmaxf(g_kcnt[b][tid], 1.f);
        km[tid] = make_float4(g_ksum[b][tid][0] * inv, g_ksum[b][tid][1] * inv,
                              g_ksum[b][tid][2] * inv, g_ksum[b][tid][3] * inv);
    }
    __syncthreads();

    u64 acc[NTAG];                // packed (sum_loss, count) per tag
#pragma unroll
    for (int t = 0; t < NTAG; t++) acc[t] = 0ull;
    unsigned pt = 0u;

    const int base = b * PIX;
    const int svb  = b * NC * PIX;
    const int off0 = chk * CHUNK + tid * 4;

#pragma unroll 1
    for (int it = 0; it < ITERS; ++it) {
        const int i = off0 + it * (TPB * 4);
        const int4 tt = *(const int4*)(text + base + i);
        const int4 mm = *(const int4*)(mask + base + i);
        float4 v[NC];
#pragma unroll
        for (int c = 0; c < NC; c++)
            v[c] = *(const float4*)(sv + svb + c * PIX + i);
        const int ta[4] = {tt.x, tt.y, tt.z, tt.w};
        const int ma[4] = {mm.x, mm.y, mm.z, mm.w};

#pragma unroll
        for (int j = 0; j < 4; j++) {
            const int tx = ta[j];
            const unsigned mbit = (ma[j] != 0) ? ~0u : 0u;
            pt |= (1u << tx) & mbit;
            const int ix = (tx != 0) ? tx - 1 : 0;          // safe gather index
            const float4 m = km[ix];
            const float d0 = f4get(v[0], j) - m.x;
            const float d1 = f4get(v[1], j) - m.y;
            const float d2 = f4get(v[2], j) - m.z;
            const float d3 = f4get(v[3], j) - m.w;
            const float ss = fmaf(d0, d0, fmaf(d1, d1, fmaf(d2, d2, d3 * d3)));
            const float dist = sqrtf(fmaxf(ss, 1e-12f));
            const float h = fmaxf(dist - 0.5f, 0.f);
            const float L = __logf(fmaf(h, h, 1.f));
            const u64 Lp = pack2(L, 1.f);
            // branchless per-tag packed accumulate (loss, count) in one FFMA2
#pragma unroll
            for (int t = 0; t < NTAG; t++) {
                const float w = (tx == t + 1) ? 1.f : 0.f;
                fma2(acc[t], pack2(w, w), Lp);
            }
        }
    }
    pt &= ~1u;

    float red[2 * NTAG];
#pragma unroll
    for (int t = 0; t < NTAG; t++) {
        const float2 a = unpack2(acc[t]);
        red[t] = a.x; red[NTAG + t] = a.y;
    }
#pragma unroll
    for (int k = 0; k < 2 * NTAG; k++) red[k] = wsum(red[k]);
    pt = __reduce_or_sync(0xffffffffu, pt);

    __shared__ float    shacc[2 * NTAG];
    __shared__ unsigned shp;
    if (tid < 2 * NTAG) shacc[tid] = 0.f;
    if (tid == 0) shp = 0u;
    __syncthreads();
    if ((tid & 31) == 0) {
#pragma unroll
        for (int k = 0; k < 2 * NTAG; k++) atomicAdd(&shacc[k], red[k]);
        atomicOr(&shp, pt);
    }
    __syncthreads();
    if (tid < NTAG) {
        atomicAdd(&g_tsum[b][tid], shacc[tid]);
    } else if (tid < 2 * NTAG) {
        atomicAdd(&g_tcnt[b][tid - NTAG], shacc[tid]);
    } else if (tid == 2 * NTAG) {
        atomicOr(&g_presT[b], shp);
    }
}

// ---------------- kernel 3: final scalar reduction + scratch re-zero ----------------
__global__ void final_reduce(float* __restrict__ out) {
    const int b = threadIdx.x;  // 32 lanes, first 16 are batches
    float contrib = 0.f, valid = 0.f;
    if (b < NB) {
        const unsigned pk = g_presK[b] & 0x1FEu;
        const unsigned pt = g_presT[b] & 0x1FEu;
        const int nk = __popc(pk), nt = __popc(pt);
        const bool bval = (nk >= 1) && (nt >= 1) && (nk == nt);
        const unsigned tv = pk & pt;
        float sum = 0.f;
        int nv = 0;
#pragma unroll
        for (int t = 1; t <= NTAG; t++) {
            if ((tv >> t) & 1u) {
                sum += g_tsum[b][t - 1] / fmaxf(g_tcnt[b][t - 1], 1.f);
                nv++;
            }
        }
        const float per = (nv > 0) ? sum / (float)nv : 0.f;
        contrib = bval ? per : 0.f;
        valid   = bval ? 1.f : 0.f;
    }
    contrib = wsum(contrib);
    valid   = wsum(valid);
    if (b == 0) out[0] = (valid > 0.f) ? contrib / valid : 0.f;

    // re-zero scratch for the next call (zero at load, re-zeroed every call)
    float* ks = &g_ksum[0][0][0];
#pragma unroll
    for (int j = b; j < NB * NTAG * NC; j += 32) ks[j] = 0.f;
#pragma unroll
    for (int j = b; j < NB * NTAG; j += 32) {
        (&g_kcnt[0][0])[j] = 0.f;
        (&g_tsum[0][0])[j] = 0.f;
        (&g_tcnt[0][0])[j] = 0.f;
    }
    if (b < NB) { g_presK[b] = 0u; g_presT[b] = 0u; }
}

// ---------------- launch ----------------
extern "C" void kernel_launch(void* const* d_in, const int* in_sizes, int n_in,
                              void* d_out, int out_size) {
    const int*   text = (const int*)d_in[0];   // gt_text_key
    const int*   kern = (const int*)d_in[1];   // gt_kernel_key
    const int*   mask = (const int*)d_in[2];   // training_mask
    const float* sv   = (const float*)d_in[3]; // similarity_vector
    float* out = (float*)d_out;

    pass1<<<dim3(CPB, NB), TPB>>>(kern, mask, sv);
    pass2<<<dim3(CPB, NB), TPB>>>(text, mask, sv);
    final_reduce<<<1, 32>>>(out);
}